// round 13
// baseline (speedup 1.0000x reference)
#include <cuda_runtime.h>
#include <math.h>

#define B_    256
#define N_    1152
#define C_    10
#define IN_   8
#define KO_   160
#define NG_   8                    // n per CTA
#define GRID_ 144                  // N_/NG_
#define NT_   1024                 // threads per gemm CTA

typedef unsigned long long u64;

#define WS2_ELEMS (NG_ * KO_ * IN_)          // 10240 u64 = 80 KB
#define DYN_BYTES (WS2_ELEMS * 8)

// partials layout [ko][slab][b]
__device__ float g_p[(size_t)KO_ * GRID_ * B_];
__device__ float g_xT[(size_t)N_ * IN_ * B_];
__device__ float g_vT[KO_ * B_];
__device__ float g_bij[N_ * C_];

// ---- packed f32x2 helpers --------------------------------------------------
__device__ __forceinline__ u64 pk(float lo, float hi) {
    u64 d; asm("mov.b64 %0, {%1, %2};" : "=l"(d) : "f"(lo), "f"(hi)); return d;
}
__device__ __forceinline__ void upk(u64 d, float& lo, float& hi) {
    asm("mov.b64 {%0, %1}, %2;" : "=f"(lo), "=f"(hi) : "l"(d));
}
__device__ __forceinline__ u64 fma2(u64 a, u64 b, u64 c) {
    u64 d; asm("fma.rn.f32x2 %0, %1, %2, %3;" : "=l"(d) : "l"(a), "l"(b), "l"(c));
    return d;
}

__global__ void noop_k() {}
__global__ void zero_bij() { g_bij[blockIdx.x * 256 + threadIdx.x] = 0.f; }

// ---------------------------------------------------------------------------
// K0: transpose x[b][(n,i)] -> xT[(n,i)][b].
// ---------------------------------------------------------------------------
__global__ __launch_bounds__(256) void xpose(const float* __restrict__ x)
{
    __shared__ float tile[32][33];
    const int cb = blockIdx.x * 32, bb = blockIdx.y * 32;
    const int tx = threadIdx.x, ty = threadIdx.y;
#pragma unroll
    for (int k = 0; k < 4; k++)
        tile[ty + 8 * k][tx] = x[(size_t)(bb + ty + 8 * k) * (N_ * IN_) + cb + tx];
    __syncthreads();
#pragma unroll
    for (int k = 0; k < 4; k++)
        g_xT[(size_t)(cb + ty + 8 * k) * B_ + bb + tx] = tile[tx][ty + 8 * k];
}

extern __shared__ u64 dynsm[];   // packed W: 80 KB (16B-aligned)

// ---------------------------------------------------------------------------
// s-mainloop: thread owns b-pair bp and kg; ko = kg + 8*jj, 4 quarters of 5.
// W read as LDS.128 (ulonglong2): 1 LDS feeds 2 fma2.
// ---------------------------------------------------------------------------
__device__ __forceinline__ void s_mainloop(const u64* Wc2, int n0, int slab,
                                           int bp, int kg)
{
    for (int koq = 0; koq < 4; koq++) {
        u64 sp[5];
#pragma unroll
        for (int j = 0; j < 5; j++) sp[j] = 0ull;

        for (int nn = 0; nn < NG_; nn++) {
            const int n = n0 + nn;
            u64 xp[IN_];
#pragma unroll
            for (int i = 0; i < IN_; i++) {
                float2 xv = __ldg((const float2*)(g_xT + ((size_t)n * IN_ + i) * B_) + bp);
                xp[i] = pk(xv.x, xv.y);
            }
            const u64* wn = Wc2 + nn * (KO_ * IN_) + kg * IN_;
#pragma unroll
            for (int j = 0; j < 5; j++) {
                const ulonglong2* wj2 =
                    (const ulonglong2*)(wn + 64 * (koq * 5 + j));
                u64 acc = sp[j];
#pragma unroll
                for (int ip = 0; ip < 4; ip++) {
                    const ulonglong2 wv = wj2[ip];       // LDS.128 broadcast
                    acc = fma2(wv.x, xp[2 * ip],     acc);
                    acc = fma2(wv.y, xp[2 * ip + 1], acc);
                }
                sp[j] = acc;
            }
        }
#pragma unroll
        for (int j = 0; j < 5; j++) {
            const int ko = kg + 8 * (koq * 5 + j);
            ((u64*)(g_p + ((size_t)ko * GRID_ + slab) * B_))[bp] = sp[j];
        }
    }
}

// ---------------------------------------------------------------------------
// S0: uniform c = 1/C folded into W at staging. 1024 threads.
// ---------------------------------------------------------------------------
__global__ __launch_bounds__(NT_, 1) void s_fold(const float* __restrict__ W)
{
    u64* Wc2 = dynsm;
    const int t = threadIdx.x, bp = t & 127, kg = t >> 7;
    const int n0 = blockIdx.x * NG_;

    for (int j = t; j < WS2_ELEMS; j += NT_) {
        float w = __ldg(&W[(size_t)(n0 + j / 1280) * 1280 + (j % 1280)]) * 0.1f;
        Wc2[j] = pk(w, w);
    }
    __syncthreads();
    s_mainloop(Wc2, n0, blockIdx.x, bp, kg);
}

// ---------------------------------------------------------------------------
// AS-fused: a-dots (u on the fly, LDS.128 W) -> batched softmax ->
// in-place rescale W by c -> s-mainloop. 1024 threads.
// ---------------------------------------------------------------------------
__global__ __launch_bounds__(NT_, 1) void as_fused(const float* __restrict__ W)
{
    u64* Ws2 = dynsm;
    __shared__ float wredN[NG_][32][C_];   // 10.2 KB
    __shared__ float cs[NG_][C_];
    const int t = threadIdx.x, bp = t & 127, kg = t >> 7;
    const int wid = t >> 5, lane = t & 31;
    const int n0 = blockIdx.x * NG_;

    for (int j = t; j < WS2_ELEMS; j += NT_) {
        float w = __ldg(&W[(size_t)(n0 + j / 1280) * 1280 + (j % 1280)]);
        Ws2[j] = pk(w, w);
    }
    __syncthreads();

    // ---- a-phase ----
    for (int nn = 0; nn < NG_; nn++) {
        const int n = n0 + nn;
        u64 xp[IN_];
#pragma unroll
        for (int i = 0; i < IN_; i++) {
            float2 xv = __ldg((const float2*)(g_xT + ((size_t)n * IN_ + i) * B_) + bp);
            xp[i] = pk(xv.x, xv.y);
        }
        const u64* wn = Ws2 + nn * (KO_ * IN_) + kg * IN_;

        float acc[C_];
#pragma unroll
        for (int k = 0; k < C_; k++) acc[k] = 0.f;
#pragma unroll
        for (int jj = 0; jj < 20; jj++) {
            const ulonglong2* wj2 = (const ulonglong2*)(wn + 64 * jj);
            u64 u = 0ull;
#pragma unroll
            for (int ip = 0; ip < 4; ip++) {
                const ulonglong2 wv = wj2[ip];           // LDS.128 broadcast
                u = fma2(wv.x, xp[2 * ip],     u);
                u = fma2(wv.y, xp[2 * ip + 1], u);
            }
            const int ko = kg + 8 * jj;
            float2 v = __ldg((const float2*)(g_vT + (size_t)ko * B_) + bp);
            float ulo, uhi; upk(u, ulo, uhi);
            acc[jj >> 1] = fmaf(ulo, v.x, fmaf(uhi, v.y, acc[jj >> 1]));
        }
#pragma unroll
        for (int k = 0; k < C_; k++) {
            float a = acc[k];
#pragma unroll
            for (int m = 16; m >= 1; m >>= 1)
                a += __shfl_xor_sync(0xffffffffu, a, m);
            if (lane == 0) wredN[nn][wid][k] = a;
        }
    }
    __syncthreads();

    // ---- batched softmax: warp wid (<8) handles n0+wid ----
    if (wid < NG_ && lane < 16) {
        const int n = n0 + wid;
        float bn = -1e30f;
        if (lane < C_) {
            float a = 0.f;
#pragma unroll
            for (int w = 0; w < 32; w++) a += wredN[wid][w][lane];
            bn = a * (1.0f / (float)B_) + g_bij[n * C_ + lane];
            g_bij[n * C_ + lane] = bn;
        }
        float mx = bn;
#pragma unroll
        for (int m = 8; m >= 1; m >>= 1)
            mx = fmaxf(mx, __shfl_xor_sync(0x0000ffffu, mx, m, 16));
        float e = (lane < C_) ? expf(bn - mx) : 0.f;
        float sm = e;
#pragma unroll
        for (int m = 8; m >= 1; m >>= 1)
            sm += __shfl_xor_sync(0x0000ffffu, sm, m, 16);
        if (lane < C_) cs[wid][lane] = e / sm;
    }
    __syncthreads();

    // ---- rescale W in place: Wc = c[n,k] * W ----
    for (int j = t; j < WS2_ELEMS; j += NT_) {
        const int nl = j / 1280, rem = j - nl * 1280;
        const int k = rem >> 7;
        float lo, hi; upk(Ws2[j], lo, hi);
        float w = lo * cs[nl][k];
        Ws2[j] = pk(w, w);
    }
    __syncthreads();

    // ---- s-phase ----
    s_mainloop(Ws2, n0, blockIdx.x, bp, kg);
}

// ---------------------------------------------------------------------------
// Reduce 144 slabs ([ko][slab][b]: 1KB strides) + squash.
// Grid (160 ko, 4 bq), 512 thr = 16 quads x 32 slab-groups (5/4 split).
// ---------------------------------------------------------------------------
__global__ __launch_bounds__(512) void reduce_sq(int final_out, float* __restrict__ out)
{
    __shared__ float4 red[32][16];
    const int ko = blockIdx.x, q = blockIdx.y, t = threadIdx.x;
    const int quad = t & 15, sg = t >> 4;               // sg 0..31
    const int start = (sg < 16) ? sg * 5 : 80 + (sg - 16) * 4;
    const int cnt   = (sg < 16) ? 5 : 4;

    const float4* pp = (const float4*)(g_p + (size_t)ko * GRID_ * B_) + q * 16 + quad;
    const size_t str = B_ / 4;

    float4 s = make_float4(0.f, 0.f, 0.f, 0.f);
#pragma unroll 5
    for (int j = 0; j < cnt; j++) {
        float4 p = pp[(size_t)(start + j) * str];
        s.x += p.x; s.y += p.y; s.z += p.z; s.w += p.w;
    }
    red[sg][quad] = s;
    __syncthreads();

    if (t < 16) {
        float4 a = red[0][t];
#pragma unroll
        for (int g = 1; g < 32; g++) {
            float4 p = red[g][t];
            a.x += p.x; a.y += p.y; a.z += p.z; a.w += p.w;
        }
        float4 v;
        v.x = a.x * fabsf(a.x) / (1.0f + a.x * a.x);
        v.y = a.y * fabsf(a.y) / (1.0f + a.y * a.y);
        v.z = a.z * fabsf(a.z) / (1.0f + a.z * a.z);
        v.w = a.w * fabsf(a.w) / (1.0f + a.w * a.w);
        if (final_out) {
            const int b0 = q * 64 + t * 4;
            out[(b0 + 0) * KO_ + ko] = v.x;
            out[(b0 + 1) * KO_ + ko] = v.y;
            out[(b0 + 2) * KO_ + ko] = v.z;
            out[(b0 + 3) * KO_ + ko] = v.w;
        } else {
            ((float4*)g_vT)[ko * 64 + q * 16 + t] = v;
        }
    }
}

// ---------------------------------------------------------------------------
extern "C" void kernel_launch(void* const* d_in, const int* in_sizes, int n_in,
                              void* d_out, int out_size)
{
    const float* x = (const float*)d_in[0];
    const float* W = (const float*)d_in[1];
    if (in_sizes[0] == N_ * C_ * 16 * IN_) { const float* t = x; x = W; W = t; }
    float* out = (float*)d_out;

    cudaFuncSetAttribute(s_fold,   cudaFuncAttributeMaxDynamicSharedMemorySize, DYN_BYTES);
    cudaFuncSetAttribute(as_fused, cudaFuncAttributeMaxDynamicSharedMemorySize, DYN_BYTES);

    zero_bij<<<45, 256>>>();                                  // #0
    xpose<<<dim3(N_ * IN_ / 32, B_ / 32), dim3(32, 8)>>>(x);  // #1
    noop_k<<<1, 32>>>();                                      // #2 (capture pad)
    s_fold<<<GRID_, NT_, DYN_BYTES>>>(W);                     // #3  <- ncu slot
    reduce_sq<<<dim3(KO_, 4), 512>>>(0, nullptr);             // #4  v0
    as_fused<<<GRID_, NT_, DYN_BYTES>>>(W);                   // #5  a0+s1
    reduce_sq<<<dim3(KO_, 4), 512>>>(0, nullptr);             // #6  v1
    as_fused<<<GRID_, NT_, DYN_BYTES>>>(W);                   // #7  a1+s2
    reduce_sq<<<dim3(KO_, 4), 512>>>(1, out);                 // #8  v2 -> d_out
}

// round 14
// speedup vs baseline: 1.4814x; 1.4814x over previous
#include <cuda_runtime.h>
#include <math.h>

#define B_    256
#define N_    1152
#define C_    10
#define IN_   8
#define KO_   160
#define NG_   8                    // n per CTA
#define GRID_ 144                  // N_/NG_

typedef unsigned long long u64;

#define WS2_ELEMS (NG_ * KO_ * IN_)          // 10240 u64 = 80 KB
#define DYN_BYTES (WS2_ELEMS * 8)

// partials layout [ko][slab][b]
__device__ float g_p[(size_t)KO_ * GRID_ * B_];
__device__ float g_xT[(size_t)N_ * IN_ * B_];
__device__ float g_vT[KO_ * B_];
__device__ float g_bij[N_ * C_];

// ---- packed f32x2 helpers --------------------------------------------------
__device__ __forceinline__ u64 pk(float lo, float hi) {
    u64 d; asm("mov.b64 %0, {%1, %2};" : "=l"(d) : "f"(lo), "f"(hi)); return d;
}
__device__ __forceinline__ void upk(u64 d, float& lo, float& hi) {
    asm("mov.b64 {%0, %1}, %2;" : "=f"(lo), "=f"(hi) : "l"(d));
}
__device__ __forceinline__ u64 fma2(u64 a, u64 b, u64 c) {
    u64 d; asm("fma.rn.f32x2 %0, %1, %2, %3;" : "=l"(d) : "l"(a), "l"(b), "l"(c));
    return d;
}

__global__ void noop_k() {}
__global__ void zero_bij() { g_bij[blockIdx.x * 256 + threadIdx.x] = 0.f; }

// ---------------------------------------------------------------------------
// K0: transpose x[b][(n,i)] -> xT[(n,i)][b].
// ---------------------------------------------------------------------------
__global__ __launch_bounds__(256) void xpose(const float* __restrict__ x)
{
    __shared__ float tile[32][33];
    const int cb = blockIdx.x * 32, bb = blockIdx.y * 32;
    const int tx = threadIdx.x, ty = threadIdx.y;
#pragma unroll
    for (int k = 0; k < 4; k++)
        tile[ty + 8 * k][tx] = x[(size_t)(bb + ty + 8 * k) * (N_ * IN_) + cb + tx];
    __syncthreads();
#pragma unroll
    for (int k = 0; k < 4; k++)
        g_xT[(size_t)(cb + ty + 8 * k) * B_ + bb + tx] = tile[tx][ty + 8 * k];
}

extern __shared__ u64 dynsm[];   // packed W: 80 KB (16B-aligned)

// ---------------------------------------------------------------------------
// s-mainloop (R11 structure): thread owns b-quad bq and kg; ko = kg + 8j,
// 2 ko-halves of 10 j. W read as LDS.128 (1 load -> 4 fma2).
// ---------------------------------------------------------------------------
__device__ __forceinline__ void s_mainloop(const u64* Wc2, int n0, int slab,
                                           int bq, int kg)
{
    for (int koh = 0; koh < 2; koh++) {
        u64 sp[10][2];
#pragma unroll
        for (int j = 0; j < 10; j++) { sp[j][0] = 0ull; sp[j][1] = 0ull; }

        for (int nn = 0; nn < NG_; nn++) {
            const int n = n0 + nn;
            u64 xp[IN_][2];
#pragma unroll
            for (int i = 0; i < IN_; i++) {
                float4 xv = __ldg((const float4*)(g_xT + ((size_t)n * IN_ + i) * B_) + bq);
                xp[i][0] = pk(xv.x, xv.y);
                xp[i][1] = pk(xv.z, xv.w);
            }
            const u64* wn = Wc2 + nn * (KO_ * IN_) + (koh * 80 + kg) * IN_;
#pragma unroll
            for (int j = 0; j < 10; j++) {
                const ulonglong2* wj2 = (const ulonglong2*)(wn + j * 64);
#pragma unroll
                for (int ip = 0; ip < 4; ip++) {
                    const ulonglong2 wv = wj2[ip];      // LDS.128 broadcast
                    sp[j][0] = fma2(wv.x, xp[2 * ip][0],     sp[j][0]);
                    sp[j][1] = fma2(wv.x, xp[2 * ip][1],     sp[j][1]);
                    sp[j][0] = fma2(wv.y, xp[2 * ip + 1][0], sp[j][0]);
                    sp[j][1] = fma2(wv.y, xp[2 * ip + 1][1], sp[j][1]);
                }
            }
        }
#pragma unroll
        for (int j = 0; j < 10; j++) {
            const int ko = koh * 80 + kg + 8 * j;
            u64* op = (u64*)(g_p + ((size_t)ko * GRID_ + slab) * B_ + bq * 4);
            op[0] = sp[j][0];
            op[1] = sp[j][1];
        }
    }
}

// ---------------------------------------------------------------------------
// S0: uniform c = 1/C folded into W at staging. 512 threads (R11 config).
// ---------------------------------------------------------------------------
__global__ __launch_bounds__(512, 1) void s_fold(const float* __restrict__ W)
{
    u64* Wc2 = dynsm;
    const int t = threadIdx.x, bq = t & 63, kg = t >> 6;
    const int n0 = blockIdx.x * NG_;

    for (int j = t; j < WS2_ELEMS; j += 512) {
        float w = __ldg(&W[(size_t)(n0 + j / 1280) * 1280 + (j % 1280)]) * 0.1f;
        Wc2[j] = pk(w, w);
    }
    __syncthreads();
    s_mainloop(Wc2, n0, blockIdx.x, bq, kg);
}

// ---------------------------------------------------------------------------
// AS-fused (R11 structure + LDS.128): a-dots -> batched softmax ->
// in-place W rescale -> s-mainloop. 512 threads.
// ---------------------------------------------------------------------------
__global__ __launch_bounds__(512, 1) void as_fused(const float* __restrict__ W)
{
    u64* Ws2 = dynsm;
    __shared__ float wredN[NG_][16][C_];
    __shared__ float cs[NG_][C_];
    const int t = threadIdx.x, bq = t & 63, kg = t >> 6;
    const int wid = t >> 5, lane = t & 31;
    const int n0 = blockIdx.x * NG_;

    for (int j = t; j < WS2_ELEMS; j += 512) {
        float w = __ldg(&W[(size_t)(n0 + j / 1280) * 1280 + (j % 1280)]);
        Ws2[j] = pk(w, w);
    }
    __syncthreads();

    // ---- a-phase ----
    for (int nn = 0; nn < NG_; nn++) {
        const int n = n0 + nn;
        u64 xp[IN_][2];
#pragma unroll
        for (int i = 0; i < IN_; i++) {
            float4 xv = __ldg((const float4*)(g_xT + ((size_t)n * IN_ + i) * B_) + bq);
            xp[i][0] = pk(xv.x, xv.y);
            xp[i][1] = pk(xv.z, xv.w);
        }
        const u64* wn = Ws2 + nn * (KO_ * IN_) + kg * IN_;

        u64 acc2[C_];
#pragma unroll
        for (int k = 0; k < C_; k++) acc2[k] = 0ull;
#pragma unroll
        for (int j = 0; j < 20; j++) {
            const ulonglong2* wj2 = (const ulonglong2*)(wn + j * 64);
            u64 u0 = 0ull, u1 = 0ull;
#pragma unroll
            for (int ip = 0; ip < 4; ip++) {
                const ulonglong2 wv = wj2[ip];          // LDS.128 broadcast
                u0 = fma2(wv.x, xp[2 * ip][0],     u0);
                u1 = fma2(wv.x, xp[2 * ip][1],     u1);
                u0 = fma2(wv.y, xp[2 * ip + 1][0], u0);
                u1 = fma2(wv.y, xp[2 * ip + 1][1], u1);
            }
            float4 v4 = __ldg((const float4*)(g_vT + (size_t)(kg + 8 * j) * B_) + bq);
            acc2[j >> 1] = fma2(u0, pk(v4.x, v4.y), acc2[j >> 1]);
            acc2[j >> 1] = fma2(u1, pk(v4.z, v4.w), acc2[j >> 1]);
        }
#pragma unroll
        for (int k = 0; k < C_; k++) {
            float lo, hi;  upk(acc2[k], lo, hi);
            float a = lo + hi;
#pragma unroll
            for (int m = 16; m >= 1; m >>= 1)
                a += __shfl_xor_sync(0xffffffffu, a, m);
            if (lane == 0) wredN[nn][wid][k] = a;
        }
    }
    __syncthreads();

    // ---- batched softmax: warp wid (<8) handles n0+wid ----
    if (wid < NG_ && lane < 16) {
        const int n = n0 + wid;
        float bn = -1e30f;
        if (lane < C_) {
            float a = 0.f;
#pragma unroll
            for (int w = 0; w < 16; w++) a += wredN[wid][w][lane];
            bn = a * (1.0f / (float)B_) + g_bij[n * C_ + lane];
            g_bij[n * C_ + lane] = bn;
        }
        float mx = bn;
#pragma unroll
        for (int m = 8; m >= 1; m >>= 1)
            mx = fmaxf(mx, __shfl_xor_sync(0x0000ffffu, mx, m, 16));
        float e = (lane < C_) ? expf(bn - mx) : 0.f;
        float sm = e;
#pragma unroll
        for (int m = 8; m >= 1; m >>= 1)
            sm += __shfl_xor_sync(0x0000ffffu, sm, m, 16);
        if (lane < C_) cs[wid][lane] = e / sm;
    }
    __syncthreads();

    // ---- rescale W in place: Wc = c[n,k] * W ----
    for (int j = t; j < WS2_ELEMS; j += 512) {
        const int nl = j / 1280, rem = j - nl * 1280;
        const int k = rem >> 7;
        float lo, hi; upk(Ws2[j], lo, hi);
        float w = lo * cs[nl][k];
        Ws2[j] = pk(w, w);
    }
    __syncthreads();

    // ---- s-phase ----
    s_mainloop(Ws2, n0, blockIdx.x, bq, kg);
}

// ---------------------------------------------------------------------------
// Reduce 144 slabs ([ko][slab][b]: 1KB strides) + squash. (R11-verified)
// Grid (160 ko, 4 bq), 256 thr = 16 quads x 16 slab-groups (9 each).
// ---------------------------------------------------------------------------
__global__ __launch_bounds__(256) void reduce_sq(int final_out, float* __restrict__ out)
{
    __shared__ float4 red[16][16];
    const int ko = blockIdx.x, q = blockIdx.y, t = threadIdx.x;
    const int quad = t & 15, sg = t >> 4;

    const float4* pp = (const float4*)(g_p + (size_t)ko * GRID_ * B_) + q * 16 + quad;
    const size_t str = B_ / 4;

    float4 s = make_float4(0.f, 0.f, 0.f, 0.f);
#pragma unroll
    for (int j = 0; j < 9; j++) {
        float4 p = pp[(size_t)(sg * 9 + j) * str];
        s.x += p.x; s.y += p.y; s.z += p.z; s.w += p.w;
    }
    red[sg][quad] = s;
    __syncthreads();

    if (t < 16) {
        float4 a = red[0][t];
#pragma unroll
        for (int g = 1; g < 16; g++) {
            float4 p = red[g][t];
            a.x += p.x; a.y += p.y; a.z += p.z; a.w += p.w;
        }
        float4 v;
        v.x = a.x * fabsf(a.x) / (1.0f + a.x * a.x);
        v.y = a.y * fabsf(a.y) / (1.0f + a.y * a.y);
        v.z = a.z * fabsf(a.z) / (1.0f + a.z * a.z);
        v.w = a.w * fabsf(a.w) / (1.0f + a.w * a.w);
        if (final_out) {
            const int b0 = q * 64 + t * 4;
            out[(b0 + 0) * KO_ + ko] = v.x;
            out[(b0 + 1) * KO_ + ko] = v.y;
            out[(b0 + 2) * KO_ + ko] = v.z;
            out[(b0 + 3) * KO_ + ko] = v.w;
        } else {
            ((float4*)g_vT)[ko * 64 + q * 16 + t] = v;
        }
    }
}

// ---------------------------------------------------------------------------
extern "C" void kernel_launch(void* const* d_in, const int* in_sizes, int n_in,
                              void* d_out, int out_size)
{
    const float* x = (const float*)d_in[0];
    const float* W = (const float*)d_in[1];
    if (in_sizes[0] == N_ * C_ * 16 * IN_) { const float* t = x; x = W; W = t; }
    float* out = (float*)d_out;

    cudaFuncSetAttribute(s_fold,   cudaFuncAttributeMaxDynamicSharedMemorySize, DYN_BYTES);
    cudaFuncSetAttribute(as_fused, cudaFuncAttributeMaxDynamicSharedMemorySize, DYN_BYTES);

    zero_bij<<<45, 256>>>();                                  // #0
    xpose<<<dim3(N_ * IN_ / 32, B_ / 32), dim3(32, 8)>>>(x);  // #1
    noop_k<<<1, 32>>>();                                      // #2 (capture pad)
    s_fold<<<GRID_, 512, DYN_BYTES>>>(W);                     // #3  <- ncu slot
    reduce_sq<<<dim3(KO_, 4), 256>>>(0, nullptr);             // #4  v0
    as_fused<<<GRID_, 512, DYN_BYTES>>>(W);                   // #5  a0+s1
    reduce_sq<<<dim3(KO_, 4), 256>>>(0, nullptr);             // #6  v1
    as_fused<<<GRID_, 512, DYN_BYTES>>>(W);                   // #7  a1+s2
    reduce_sq<<<dim3(KO_, 4), 256>>>(1, out);                 // #8  v2 -> d_out
}

// round 16
// speedup vs baseline: 1.5026x; 1.0143x over previous
#include <cuda_runtime.h>
#include <cuda_bf16.h>
#include <math.h>

#define B_    256
#define N_    1152
#define C_    10
#define IN_   8
#define KO_   160
#define NG_   8                    // n per CTA -> K-slice of 64
#define GRID_ 144                  // N_/NG_

typedef unsigned long long u64;
typedef unsigned int u32;

// ---- global scratch --------------------------------------------------------
__device__ float g_p[(size_t)KO_ * GRID_ * B_];   // partials [ko][slab][b]
__device__ float g_xT[(size_t)N_ * IN_ * B_];
__device__ float g_vT[KO_ * B_];
__device__ float g_bij[N_ * C_];
__device__ float g_c[N_ * C_];

// ---- packed f32x2 helpers (scalar a-pass) ----------------------------------
__device__ __forceinline__ u64 pk(float lo, float hi) {
    u64 d; asm("mov.b64 %0, {%1, %2};" : "=l"(d) : "f"(lo), "f"(hi)); return d;
}
__device__ __forceinline__ void upk(u64 d, float& lo, float& hi) {
    asm("mov.b64 {%0, %1}, %2;" : "=f"(lo), "=f"(hi) : "l"(d));
}
__device__ __forceinline__ u64 fma2(u64 a, u64 b, u64 c) {
    u64 d; asm("fma.rn.f32x2 %0, %1, %2, %3;" : "=l"(d) : "l"(a), "l"(b), "l"(c));
    return d;
}

__device__ __forceinline__ u32 smem_u32(const void* p) {
    u32 a;
    asm("{.reg .u64 t; cvta.to.shared.u64 t, %1; cvt.u32.u64 %0, t;}"
        : "=r"(a) : "l"(p));
    return a;
}
__device__ __forceinline__ void ldsm4(u32& r0, u32& r1, u32& r2, u32& r3, u32 a) {
    asm volatile("ldmatrix.sync.aligned.m8n8.x4.shared.b16 {%0,%1,%2,%3}, [%4];"
                 : "=r"(r0), "=r"(r1), "=r"(r2), "=r"(r3) : "r"(a));
}
__device__ __forceinline__ void mma16816(float* c, u32 a0, u32 a1, u32 a2, u32 a3,
                                         u32 b0, u32 b1) {
    asm volatile(
        "mma.sync.aligned.m16n8k16.row.col.f32.bf16.bf16.f32 "
        "{%0,%1,%2,%3}, {%4,%5,%6,%7}, {%8,%9}, {%0,%1,%2,%3};"
        : "+f"(c[0]), "+f"(c[1]), "+f"(c[2]), "+f"(c[3])
        : "r"(a0), "r"(a1), "r"(a2), "r"(a3), "r"(b0), "r"(b1));
}

__global__ void noop_k() {}
__global__ void zero_bij() { g_bij[blockIdx.x * 256 + threadIdx.x] = 0.f; }

// ---------------------------------------------------------------------------
// K0: transpose x[b][(n,i)] -> xT[(n,i)][b]  (a_gemm input).
// ---------------------------------------------------------------------------
__global__ __launch_bounds__(256) void xpose(const float* __restrict__ x)
{
    __shared__ float tile[32][33];
    const int cb = blockIdx.x * 32, bb = blockIdx.y * 32;
    const int tx = threadIdx.x, ty = threadIdx.y;
#pragma unroll
    for (int k = 0; k < 4; k++)
        tile[ty + 8 * k][tx] = x[(size_t)(bb + ty + 8 * k) * (N_ * IN_) + cb + tx];
    __syncthreads();
#pragma unroll
    for (int k = 0; k < 4; k++)
        g_xT[(size_t)(cb + ty + 8 * k) * B_ + bb + tx] = tile[tx][ty + 8 * k];
}

extern __shared__ char dynraw[];

// ---------------------------------------------------------------------------
// S-pass via mma.sync bf16 split: D[b,ko] = sum_k A[b,k]*B[ko,k], K=64/CTA.
// A rows = b (256), B rows = ko (160); row pitch 144B (conflict-free ldmatrix).
// 3 products: A0*B0 + A0*B1 + A1*B0. 16 warps x 1 m-tile (16 b-rows).
// ---------------------------------------------------------------------------
#define PITCH_ 144
#define SA0_ 0
#define SA1_ (SA0_ + B_ * PITCH_)          // 36864
#define SB0_ (SA1_ + B_ * PITCH_)          // 73728
#define SB1_ (SB0_ + KO_ * PITCH_)         // 96768
#define S_TC_BYTES (SB1_ + KO_ * PITCH_)   // 119808

__global__ __launch_bounds__(512, 1) void s_tc(const float* __restrict__ x,
                                               const float* __restrict__ W,
                                               int uniform)
{
    const int t = threadIdx.x, wid = t >> 5, lane = t & 31;
    const int slab = blockIdx.x, n0 = slab * NG_;
    const u32 sb = smem_u32(dynraw);

    // ---- stage A: x[b][n0*8 .. n0*8+63] -> A0/A1 rows (bf16 split) ---------
    {
        const int b = t >> 1, half = t & 1;
        const float4* xr = (const float4*)(x + (size_t)b * (N_ * IN_) + n0 * IN_) + half * 8;
        char* a0r = dynraw + SA0_ + b * PITCH_ + half * 64;
        char* a1r = dynraw + SA1_ + b * PITCH_ + half * 64;
#pragma unroll
        for (int q = 0; q < 8; q++) {
            float4 xv = __ldg(xr + q);
            __nv_bfloat16 hx = __float2bfloat16(xv.x), hy = __float2bfloat16(xv.y);
            __nv_bfloat16 hz = __float2bfloat16(xv.z), hw = __float2bfloat16(xv.w);
            __nv_bfloat162 p0; p0.x = hx; p0.y = hy;
            __nv_bfloat162 p1; p1.x = hz; p1.y = hw;
            *(__nv_bfloat162*)(a0r + q * 8)     = p0;
            *(__nv_bfloat162*)(a0r + q * 8 + 4) = p1;
            __nv_bfloat162 r0, r1;
            r0.x = __float2bfloat16(xv.x - __bfloat162float(hx));
            r0.y = __float2bfloat16(xv.y - __bfloat162float(hy));
            r1.x = __float2bfloat16(xv.z - __bfloat162float(hz));
            r1.y = __float2bfloat16(xv.w - __bfloat162float(hw));
            *(__nv_bfloat162*)(a1r + q * 8)     = r0;
            *(__nv_bfloat162*)(a1r + q * 8 + 4) = r1;
        }
    }
    // ---- stage B: Wc[ko][kappa] = c[n,k]*W[n,ko,i] (bf16 split) ------------
    for (int j = t; j < KO_ * 64; j += 512) {
        const int nn = j / 1280, rem = j % 1280;
        const int ko = rem >> 3, i = rem & 7;
        const int kap = nn * 8 + i;
        float w = __ldg(&W[(size_t)(n0 + nn) * 1280 + rem]);
        float c = uniform ? 0.1f : __ldg(&g_c[(n0 + nn) * C_ + (ko >> 4)]);
        w *= c;
        __nv_bfloat16 h1 = __float2bfloat16(w);
        *(__nv_bfloat16*)(dynraw + SB0_ + ko * PITCH_ + kap * 2) = h1;
        *(__nv_bfloat16*)(dynraw + SB1_ + ko * PITCH_ + kap * 2) =
            __float2bfloat16(w - __bfloat162float(h1));
    }
    __syncthreads();

    // ---- MMA mainloop: warp owns b-rows m0..m0+15 ---------------------------
    const int m0 = wid * 16;
    float acc[20][4];
#pragma unroll
    for (int nt = 0; nt < 20; nt++)
#pragma unroll
        for (int q = 0; q < 4; q++) acc[nt][q] = 0.f;

    // A frag address: row m0 + (lane&15), col byte (k0 + (lane>>4)*8)*2
    const int ar = lane & 15, ac = (lane >> 4) * 16;
    // B frag x4 address: covers 2 n-tiles (16 ko rows) x full k-step
    const int br = lane & 7, bsel = lane >> 3;
    const int brow_off = ((bsel >> 1) & 1) * 8;     // +8 ko rows for sel 2,3
    const int bcol_off = (bsel & 1) * 16;           // +8 k (16 bytes) for sel 1,3

    const u32 abase[3] = { sb + SA0_, sb + SA0_, sb + SA1_ };
    const u32 bbase[3] = { sb + SB0_, sb + SB1_, sb + SB0_ };

#pragma unroll
    for (int pp = 0; pp < 3; pp++) {
        const u32 ab = abase[pp] + (m0 + ar) * PITCH_ + ac;
        const u32 bb = bbase[pp] + (br + brow_off) * PITCH_ + bcol_off;
#pragma unroll
        for (int kc = 0; kc < 4; kc++) {
            u32 a0, a1, a2, a3;
            ldsm4(a0, a1, a2, a3, ab + kc * 32);
#pragma unroll
            for (int nt = 0; nt < 10; nt++) {
                u32 b0, b1, b2, b3;
                ldsm4(b0, b1, b2, b3, bb + nt * 16 * PITCH_ + kc * 32);
                mma16816(acc[2 * nt],     a0, a1, a2, a3, b0, b1);
                mma16816(acc[2 * nt + 1], a0, a1, a2, a3, b2, b3);
            }
        }
    }

    // ---- epilogue: write partials [ko][slab][b] -----------------------------
    const int g = lane >> 2, tq = lane & 3;
#pragma unroll
    for (int nt = 0; nt < 20; nt++) {
        const int ko = nt * 8 + 2 * tq;
        float* p0 = g_p + ((size_t)ko * GRID_ + slab) * B_ + m0 + g;
        float* p1 = p0 + (size_t)GRID_ * B_;        // ko+1
        p0[0] = acc[nt][0];
        p1[0] = acc[nt][1];
        p0[8] = acc[nt][2];                         // b = m0+g+8
        p1[8] = acc[nt][3];
    }
}

// ---------------------------------------------------------------------------
// A-pass (scalar, R10-verified): a[n,k] = (1/B) sum u*v (u on the fly),
// batched softmax -> g_c. 512 threads, 80KB dyn smem.
// ---------------------------------------------------------------------------
#define WS2_ELEMS (NG_ * KO_ * IN_)
#define A_DYN_BYTES (WS2_ELEMS * 8)

__global__ __launch_bounds__(512, 1) void a_gemm(const float* __restrict__ W)
{
    u64* Ws2 = (u64*)dynraw;
    __shared__ float wredN[NG_][16][C_];
    const int t = threadIdx.x, bq = t & 63, kg = t >> 6;
    const int wid = t >> 5, lane = t & 31;
    const int n0 = blockIdx.x * NG_;

    for (int j = t; j < WS2_ELEMS; j += 512) {
        float w = __ldg(&W[(size_t)(n0 + j / 1280) * 1280 + (j % 1280)]);
        Ws2[j] = pk(w, w);
    }
    __syncthreads();

    for (int nn = 0; nn < NG_; nn++) {
        const int n = n0 + nn;
        u64 xp[IN_][2];
#pragma unroll
        for (int i = 0; i < IN_; i++) {
            float4 xv = __ldg((const float4*)(g_xT + ((size_t)n * IN_ + i) * B_) + bq);
            xp[i][0] = pk(xv.x, xv.y);
            xp[i][1] = pk(xv.z, xv.w);
        }
        const u64* wn = Ws2 + nn * (KO_ * IN_) + kg * IN_;

        u64 acc2[C_];
#pragma unroll
        for (int k = 0; k < C_; k++) acc2[k] = 0ull;
#pragma unroll
        for (int j = 0; j < 20; j++) {
            const u64* wj = wn + j * 64;
            u64 u0 = 0ull, u1 = 0ull;
#pragma unroll
            for (int i = 0; i < IN_; i++) {
                const u64 wv = wj[i];
                u0 = fma2(wv, xp[i][0], u0);
                u1 = fma2(wv, xp[i][1], u1);
            }
            float4 v4 = __ldg((const float4*)(g_vT + (size_t)(kg + 8 * j) * B_) + bq);
            acc2[j >> 1] = fma2(u0, pk(v4.x, v4.y), acc2[j >> 1]);
            acc2[j >> 1] = fma2(u1, pk(v4.z, v4.w), acc2[j >> 1]);
        }
#pragma unroll
        for (int k = 0; k < C_; k++) {
            float lo, hi;  upk(acc2[k], lo, hi);
            float a = lo + hi;
#pragma unroll
            for (int m = 16; m >= 1; m >>= 1)
                a += __shfl_xor_sync(0xffffffffu, a, m);
            if (lane == 0) wredN[nn][wid][k] = a;
        }
    }
    __syncthreads();

    if (wid < NG_ && lane < 16) {
        const int n = n0 + wid;
        float bn = -1e30f;
        if (lane < C_) {
            float a = 0.f;
#pragma unroll
            for (int w = 0; w < 16; w++) a += wredN[wid][w][lane];
            bn = a * (1.0f / (float)B_) + g_bij[n * C_ + lane];
            g_bij[n * C_ + lane] = bn;
        }
        float mx = bn;
#pragma unroll
        for (int m = 8; m >= 1; m >>= 1)
            mx = fmaxf(mx, __shfl_xor_sync(0x0000ffffu, mx, m, 16));
        float e = (lane < C_) ? expf(bn - mx) : 0.f;
        float sm = e;
#pragma unroll
        for (int m = 8; m >= 1; m >>= 1)
            sm += __shfl_xor_sync(0x0000ffffu, sm, m, 16);
        if (lane < C_) g_c[n * C_ + lane] = e / sm;
    }
}

// ---------------------------------------------------------------------------
// Reduce 144 slabs ([ko][slab][b]) + squash. (R11-verified)
// ---------------------------------------------------------------------------
__global__ __launch_bounds__(256) void reduce_sq(int final_out, float* __restrict__ out)
{
    __shared__ float4 red[16][16];
    const int ko = blockIdx.x, q = blockIdx.y, t = threadIdx.x;
    const int quad = t & 15, sg = t >> 4;

    const float4* pp = (const float4*)(g_p + (size_t)ko * GRID_ * B_) + q * 16 + quad;
    const size_t str = B_ / 4;

    float4 s = make_float4(0.f, 0.f, 0.f, 0.f);
#pragma unroll
    for (int j = 0; j < 9; j++) {
        float4 p = pp[(size_t)(sg * 9 + j) * str];
        s.x += p.x; s.y += p.y; s.z += p.z; s.w += p.w;
    }
    red[sg][quad] = s;
    __syncthreads();

    if (t < 16) {
        float4 a = red[0][t];
#pragma unroll
        for (int g = 1; g < 16; g++) {
            float4 p = red[g][t];
            a.x += p.x; a.y += p.y; a.z += p.z; a.w += p.w;
        }
        float4 v;
        v.x = a.x * fabsf(a.x) / (1.0f + a.x * a.x);
        v.y = a.y * fabsf(a.y) / (1.0f + a.y * a.y);
        v.z = a.z * fabsf(a.z) / (1.0f + a.z * a.z);
        v.w = a.w * fabsf(a.w) / (1.0f + a.w * a.w);
        if (final_out) {
            const int b0 = q * 64 + t * 4;
            out[(b0 + 0) * KO_ + ko] = v.x;
            out[(b0 + 1) * KO_ + ko] = v.y;
            out[(b0 + 2) * KO_ + ko] = v.z;
            out[(b0 + 3) * KO_ + ko] = v.w;
        } else {
            ((float4*)g_vT)[ko * 64 + q * 16 + t] = v;
        }
    }
}

// ---------------------------------------------------------------------------
extern "C" void kernel_launch(void* const* d_in, const int* in_sizes, int n_in,
                              void* d_out, int out_size)
{
    const float* x = (const float*)d_in[0];
    const float* W = (const float*)d_in[1];
    if (in_sizes[0] == N_ * C_ * 16 * IN_) { const float* t = x; x = W; W = t; }
    float* out = (float*)d_out;

    cudaFuncSetAttribute(s_tc,   cudaFuncAttributeMaxDynamicSharedMemorySize, S_TC_BYTES);
    cudaFuncSetAttribute(a_gemm, cudaFuncAttributeMaxDynamicSharedMemorySize, A_DYN_BYTES);

    zero_bij<<<45, 256>>>();                                  // #0
    xpose<<<dim3(N_ * IN_ / 32, B_ / 32), dim3(32, 8)>>>(x);  // #1
    noop_k<<<1, 32>>>();                                      // #2 (capture pad)
    s_tc<<<GRID_, 512, S_TC_BYTES>>>(x, W, 1);                // #3  s0  <- ncu
    reduce_sq<<<dim3(KO_, 4), 256>>>(0, nullptr);             // #4  v0
    a_gemm<<<GRID_, 512, A_DYN_BYTES>>>(W);                   // #5  c1
    s_tc<<<GRID_, 512, S_TC_BYTES>>>(x, W, 0);                // #6  s1
    reduce_sq<<<dim3(KO_, 4), 256>>>(0, nullptr);             // #7  v1
    a_gemm<<<GRID_, 512, A_DYN_BYTES>>>(W);                   // #8  c2
    s_tc<<<GRID_, 512, S_TC_BYTES>>>(x, W, 0);                // #9  s2
    reduce_sq<<<dim3(KO_, 4), 256>>>(1, out);                 // #10 v2 -> d_out
}

// round 17
// speedup vs baseline: 1.7744x; 1.1809x over previous
#include <cuda_runtime.h>
#include <cuda_bf16.h>
#include <math.h>

#define B_    256
#define N_    1152
#define C_    10
#define IN_   8
#define KO_   160
#define NG_   8                    // n per CTA -> K-slice of 64
#define GRID_ 144                  // N_/NG_

typedef unsigned long long u64;
typedef unsigned int u32;

// ---- global scratch --------------------------------------------------------
__device__ float g_p[(size_t)KO_ * GRID_ * B_];   // partials [ko][slab][b]
__device__ float g_xT[(size_t)N_ * IN_ * B_];
__device__ float g_vT[KO_ * B_];
__device__ float g_bij[N_ * C_];
__device__ float g_c[N_ * C_];

// ---- packed f32x2 helpers (scalar a-pass) ----------------------------------
__device__ __forceinline__ u64 pk(float lo, float hi) {
    u64 d; asm("mov.b64 %0, {%1, %2};" : "=l"(d) : "f"(lo), "f"(hi)); return d;
}
__device__ __forceinline__ void upk(u64 d, float& lo, float& hi) {
    asm("mov.b64 {%0, %1}, %2;" : "=f"(lo), "=f"(hi) : "l"(d));
}
__device__ __forceinline__ u64 fma2(u64 a, u64 b, u64 c) {
    u64 d; asm("fma.rn.f32x2 %0, %1, %2, %3;" : "=l"(d) : "l"(a), "l"(b), "l"(c));
    return d;
}

__device__ __forceinline__ u32 smem_u32(const void* p) {
    u32 a;
    asm("{.reg .u64 t; cvta.to.shared.u64 t, %1; cvt.u32.u64 %0, t;}"
        : "=r"(a) : "l"(p));
    return a;
}
__device__ __forceinline__ void ldsm4(u32& r0, u32& r1, u32& r2, u32& r3, u32 a) {
    asm volatile("ldmatrix.sync.aligned.m8n8.x4.shared.b16 {%0,%1,%2,%3}, [%4];"
                 : "=r"(r0), "=r"(r1), "=r"(r2), "=r"(r3) : "r"(a));
}
__device__ __forceinline__ void mma16816(float* c, u32 a0, u32 a1, u32 a2, u32 a3,
                                         u32 b0, u32 b1) {
    asm volatile(
        "mma.sync.aligned.m16n8k16.row.col.f32.bf16.bf16.f32 "
        "{%0,%1,%2,%3}, {%4,%5,%6,%7}, {%8,%9}, {%0,%1,%2,%3};"
        : "+f"(c[0]), "+f"(c[1]), "+f"(c[2]), "+f"(c[3])
        : "r"(a0), "r"(a1), "r"(a2), "r"(a3), "r"(b0), "r"(b1));
}
__device__ __forceinline__ u32 bfpair(float a, float b) {
    __nv_bfloat162 p;
    p.x = __float2bfloat16(a); p.y = __float2bfloat16(b);
    return *(u32*)&p;
}

__global__ void noop_k() {}
__global__ void zero_bij() { g_bij[blockIdx.x * 256 + threadIdx.x] = 0.f; }

// ---------------------------------------------------------------------------
// K0: transpose x[b][(n,i)] -> xT[(n,i)][b]  (a_gemm input).
// ---------------------------------------------------------------------------
__global__ __launch_bounds__(256) void xpose(const float* __restrict__ x)
{
    __shared__ float tile[32][33];
    const int cb = blockIdx.x * 32, bb = blockIdx.y * 32;
    const int tx = threadIdx.x, ty = threadIdx.y;
#pragma unroll
    for (int k = 0; k < 4; k++)
        tile[ty + 8 * k][tx] = x[(size_t)(bb + ty + 8 * k) * (N_ * IN_) + cb + tx];
    __syncthreads();
#pragma unroll
    for (int k = 0; k < 4; k++)
        g_xT[(size_t)(cb + ty + 8 * k) * B_ + bb + tx] = tile[tx][ty + 8 * k];
}

extern __shared__ char dynraw[];

// ---------------------------------------------------------------------------
// S-pass via mma.sync bf16 split (R16-verified math, optimized supply):
// D[b,ko] = sum_k A[b,k]*B[ko,k], K=64/CTA; 3 products A0B0+A0B1+A1B0.
// ---------------------------------------------------------------------------
#define PITCH_ 144
#define SA0_ 0
#define SA1_ (SA0_ + B_ * PITCH_)          // 36864
#define SB0_ (SA1_ + B_ * PITCH_)          // 73728
#define SB1_ (SB0_ + KO_ * PITCH_)         // 96768
#define S_TC_BYTES (SB1_ + KO_ * PITCH_)   // 119808

__global__ __launch_bounds__(512, 1) void s_tc(const float* __restrict__ x,
                                               const float* __restrict__ W,
                                               int uniform)
{
    const int t = threadIdx.x, wid = t >> 5, lane = t & 31;
    const int slab = blockIdx.x, n0 = slab * NG_;
    const u32 sb = smem_u32(dynraw);

    // ---- stage A: x[b][n0*8..+63] -> A0/A1 rows, bf16 split, STS.128 -------
    {
        const int b = t >> 1, half = t & 1;
        const float4* xr = (const float4*)(x + (size_t)b * (N_ * IN_) + n0 * IN_) + half * 8;
        char* a0r = dynraw + SA0_ + b * PITCH_ + half * 64;
        char* a1r = dynraw + SA1_ + b * PITCH_ + half * 64;
#pragma unroll
        for (int qp = 0; qp < 4; qp++) {                 // q pair (2qp, 2qp+1)
            float4 x0 = __ldg(xr + 2 * qp);
            float4 x1 = __ldg(xr + 2 * qp + 1);
            uint4 hi, lo;
            hi.x = bfpair(x0.x, x0.y); hi.y = bfpair(x0.z, x0.w);
            hi.z = bfpair(x1.x, x1.y); hi.w = bfpair(x1.z, x1.w);
            // remainders
            __nv_bfloat162 h;
            *(u32*)&h = hi.x; lo.x = bfpair(x0.x - __bfloat162float(h.x), x0.y - __bfloat162float(h.y));
            *(u32*)&h = hi.y; lo.y = bfpair(x0.z - __bfloat162float(h.x), x0.w - __bfloat162float(h.y));
            *(u32*)&h = hi.z; lo.z = bfpair(x1.x - __bfloat162float(h.x), x1.y - __bfloat162float(h.y));
            *(u32*)&h = hi.w; lo.w = bfpair(x1.z - __bfloat162float(h.x), x1.w - __bfloat162float(h.y));
            *(uint4*)(a0r + qp * 16) = hi;               // STS.128 (16B aligned)
            *(uint4*)(a1r + qp * 16) = lo;
        }
    }
    // ---- stage B: Wc[ko][kappa] = c[n,k]*W[n,ko,i], float4 cells -----------
    for (int j = t; j < NG_ * KO_ * 2; j += 512) {       // 2560 cells of 4 i's
        const int nn = j / 320, rem = j - nn * 320;
        const int ko = rem >> 1, i4 = rem & 1;
        float4 wv = __ldg((const float4*)(W + (size_t)(n0 + nn) * 1280 + ko * 8 + i4 * 4));
        const float c = uniform ? 0.1f : __ldg(&g_c[(n0 + nn) * C_ + (ko >> 4)]);
        wv.x *= c; wv.y *= c; wv.z *= c; wv.w *= c;
        u32 h0 = bfpair(wv.x, wv.y), h1 = bfpair(wv.z, wv.w);
        __nv_bfloat162 hh;
        *(u32*)&hh = h0;
        u32 r0 = bfpair(wv.x - __bfloat162float(hh.x), wv.y - __bfloat162float(hh.y));
        *(u32*)&hh = h1;
        u32 r1 = bfpair(wv.z - __bfloat162float(hh.x), wv.w - __bfloat162float(hh.y));
        const int off = ko * PITCH_ + (nn * 8 + i4 * 4) * 2;   // 8B aligned
        *(u64*)(dynraw + SB0_ + off) = ((u64)h1 << 32) | h0;   // STS.64
        *(u64*)(dynraw + SB1_ + off) = ((u64)r1 << 32) | r0;
    }
    __syncthreads();

    // ---- MMA mainloop (reordered kc->nt: B frags loaded once, 6 mma each) --
    const int m0 = wid * 16;
    float acc[20][4];
#pragma unroll
    for (int nt = 0; nt < 20; nt++)
#pragma unroll
        for (int q = 0; q < 4; q++) acc[nt][q] = 0.f;

    const int ar = lane & 15, ac = (lane >> 4) * 16;
    const int br = lane & 7, bsel = lane >> 3;
    const int brow_off = ((bsel >> 1) & 1) * 8;
    const int bcol_off = (bsel & 1) * 16;

    const u32 a0b = sb + SA0_ + (m0 + ar) * PITCH_ + ac;
    const u32 a1b = sb + SA1_ + (m0 + ar) * PITCH_ + ac;
    const u32 b0b = sb + SB0_ + (br + brow_off) * PITCH_ + bcol_off;
    const u32 b1b = sb + SB1_ + (br + brow_off) * PITCH_ + bcol_off;

#pragma unroll
    for (int kc = 0; kc < 4; kc++) {
        u32 p0, p1, p2, p3, q0, q1, q2, q3;
        ldsm4(p0, p1, p2, p3, a0b + kc * 32);            // A0 frag
        ldsm4(q0, q1, q2, q3, a1b + kc * 32);            // A1 frag
#pragma unroll
        for (int nt = 0; nt < 10; nt++) {
            u32 b0, b1, b2, b3, c0, c1, c2, c3;
            ldsm4(b0, b1, b2, b3, b0b + nt * 16 * PITCH_ + kc * 32);   // B0
            ldsm4(c0, c1, c2, c3, b1b + nt * 16 * PITCH_ + kc * 32);   // B1
            mma16816(acc[2 * nt],     p0, p1, p2, p3, b0, b1);   // A0*B0
            mma16816(acc[2 * nt + 1], p0, p1, p2, p3, b2, b3);
            mma16816(acc[2 * nt],     p0, p1, p2, p3, c0, c1);   // A0*B1
            mma16816(acc[2 * nt + 1], p0, p1, p2, p3, c2, c3);
            mma16816(acc[2 * nt],     q0, q1, q2, q3, b0, b1);   // A1*B0
            mma16816(acc[2 * nt + 1], q0, q1, q2, q3, b2, b3);
        }
    }

    // ---- epilogue: write partials [ko][slab][b] (R16-verified mapping) -----
    const int g = lane >> 2, tq = lane & 3;
#pragma unroll
    for (int nt = 0; nt < 20; nt++) {
        const int ko = nt * 8 + 2 * tq;
        float* p0 = g_p + ((size_t)ko * GRID_ + slab) * B_ + m0 + g;
        float* p1 = p0 + (size_t)GRID_ * B_;
        p0[0] = acc[nt][0];
        p1[0] = acc[nt][1];
        p0[8] = acc[nt][2];
        p1[8] = acc[nt][3];
    }
}

// ---------------------------------------------------------------------------
// A-pass (scalar, R10-verified): a[n,k] = (1/B) sum u*v (u on the fly),
// batched softmax -> g_c. 512 threads, 80KB dyn smem.
// ---------------------------------------------------------------------------
#define WS2_ELEMS (NG_ * KO_ * IN_)
#define A_DYN_BYTES (WS2_ELEMS * 8)

__global__ __launch_bounds__(512, 1) void a_gemm(const float* __restrict__ W)
{
    u64* Ws2 = (u64*)dynraw;
    __shared__ float wredN[NG_][16][C_];
    const int t = threadIdx.x, bq = t & 63, kg = t >> 6;
    const int wid = t >> 5, lane = t & 31;
    const int n0 = blockIdx.x * NG_;

    for (int j = t; j < WS2_ELEMS; j += 512) {
        float w = __ldg(&W[(size_t)(n0 + j / 1280) * 1280 + (j % 1280)]);
        Ws2[j] = pk(w, w);
    }
    __syncthreads();

    for (int nn = 0; nn < NG_; nn++) {
        const int n = n0 + nn;
        u64 xp[IN_][2];
#pragma unroll
        for (int i = 0; i < IN_; i++) {
            float4 xv = __ldg((const float4*)(g_xT + ((size_t)n * IN_ + i) * B_) + bq);
            xp[i][0] = pk(xv.x, xv.y);
            xp[i][1] = pk(xv.z, xv.w);
        }
        const u64* wn = Ws2 + nn * (KO_ * IN_) + kg * IN_;

        u64 acc2[C_];
#pragma unroll
        for (int k = 0; k < C_; k++) acc2[k] = 0ull;
#pragma unroll
        for (int j = 0; j < 20; j++) {
            const u64* wj = wn + j * 64;
            u64 u0 = 0ull, u1 = 0ull;
#pragma unroll
            for (int i = 0; i < IN_; i++) {
                const u64 wv = wj[i];
                u0 = fma2(wv, xp[i][0], u0);
                u1 = fma2(wv, xp[i][1], u1);
            }
            float4 v4 = __ldg((const float4*)(g_vT + (size_t)(kg + 8 * j) * B_) + bq);
            acc2[j >> 1] = fma2(u0, pk(v4.x, v4.y), acc2[j >> 1]);
            acc2[j >> 1] = fma2(u1, pk(v4.z, v4.w), acc2[j >> 1]);
        }
#pragma unroll
        for (int k = 0; k < C_; k++) {
            float lo, hi;  upk(acc2[k], lo, hi);
            float a = lo + hi;
#pragma unroll
            for (int m = 16; m >= 1; m >>= 1)
                a += __shfl_xor_sync(0xffffffffu, a, m);
            if (lane == 0) wredN[nn][wid][k] = a;
        }
    }
    __syncthreads();

    if (wid < NG_ && lane < 16) {
        const int n = n0 + wid;
        float bn = -1e30f;
        if (lane < C_) {
            float a = 0.f;
#pragma unroll
            for (int w = 0; w < 16; w++) a += wredN[wid][w][lane];
            bn = a * (1.0f / (float)B_) + g_bij[n * C_ + lane];
            g_bij[n * C_ + lane] = bn;
        }
        float mx = bn;
#pragma unroll
        for (int m = 8; m >= 1; m >>= 1)
            mx = fmaxf(mx, __shfl_xor_sync(0x0000ffffu, mx, m, 16));
        float e = (lane < C_) ? expf(bn - mx) : 0.f;
        float sm = e;
#pragma unroll
        for (int m = 8; m >= 1; m >>= 1)
            sm += __shfl_xor_sync(0x0000ffffu, sm, m, 16);
        if (lane < C_) g_c[n * C_ + lane] = e / sm;
    }
}

// ---------------------------------------------------------------------------
// Reduce 144 slabs ([ko][slab][b]) + squash. (R11-verified)
// ---------------------------------------------------------------------------
__global__ __launch_bounds__(256) void reduce_sq(int final_out, float* __restrict__ out)
{
    __shared__ float4 red[16][16];
    const int ko = blockIdx.x, q = blockIdx.y, t = threadIdx.x;
    const int quad = t & 15, sg = t >> 4;

    const float4* pp = (const float4*)(g_p + (size_t)ko * GRID_ * B_) + q * 16 + quad;
    const size_t str = B_ / 4;

    float4 s = make_float4(0.f, 0.f, 0.f, 0.f);
#pragma unroll
    for (int j = 0; j < 9; j++) {
        float4 p = pp[(size_t)(sg * 9 + j) * str];
        s.x += p.x; s.y += p.y; s.z += p.z; s.w += p.w;
    }
    red[sg][quad] = s;
    __syncthreads();

    if (t < 16) {
        float4 a = red[0][t];
#pragma unroll
        for (int g = 1; g < 16; g++) {
            float4 p = red[g][t];
            a.x += p.x; a.y += p.y; a.z += p.z; a.w += p.w;
        }
        float4 v;
        v.x = a.x * fabsf(a.x) / (1.0f + a.x * a.x);
        v.y = a.y * fabsf(a.y) / (1.0f + a.y * a.y);
        v.z = a.z * fabsf(a.z) / (1.0f + a.z * a.z);
        v.w = a.w * fabsf(a.w) / (1.0f + a.w * a.w);
        if (final_out) {
            const int b0 = q * 64 + t * 4;
            out[(b0 + 0) * KO_ + ko] = v.x;
            out[(b0 + 1) * KO_ + ko] = v.y;
            out[(b0 + 2) * KO_ + ko] = v.z;
            out[(b0 + 3) * KO_ + ko] = v.w;
        } else {
            ((float4*)g_vT)[ko * 64 + q * 16 + t] = v;
        }
    }
}

// ---------------------------------------------------------------------------
extern "C" void kernel_launch(void* const* d_in, const int* in_sizes, int n_in,
                              void* d_out, int out_size)
{
    const float* x = (const float*)d_in[0];
    const float* W = (const float*)d_in[1];
    if (in_sizes[0] == N_ * C_ * 16 * IN_) { const float* t = x; x = W; W = t; }
    float* out = (float*)d_out;

    cudaFuncSetAttribute(s_tc,   cudaFuncAttributeMaxDynamicSharedMemorySize, S_TC_BYTES);
    cudaFuncSetAttribute(a_gemm, cudaFuncAttributeMaxDynamicSharedMemorySize, A_DYN_BYTES);

    zero_bij<<<45, 256>>>();                                  // #0
    xpose<<<dim3(N_ * IN_ / 32, B_ / 32), dim3(32, 8)>>>(x);  // #1
    noop_k<<<1, 32>>>();                                      // #2 (capture pad)
    s_tc<<<GRID_, 512, S_TC_BYTES>>>(x, W, 1);                // #3  s0  <- ncu
    reduce_sq<<<dim3(KO_, 4), 256>>>(0, nullptr);             // #4  v0
    a_gemm<<<GRID_, 512, A_DYN_BYTES>>>(W);                   // #5  c1
    s_tc<<<GRID_, 512, S_TC_BYTES>>>(x, W, 0);                // #6  s1
    reduce_sq<<<dim3(KO_, 4), 256>>>(0, nullptr);             // #7  v1
    a_gemm<<<GRID_, 512, A_DYN_BYTES>>>(W);                   // #8  c2
    s_tc<<<GRID_, 512, S_TC_BYTES>>>(x, W, 0);                // #9  s2
    reduce_sq<<<dim3(KO_, 4), 256>>>(1, out);                 // #10 v2 -> d_out
}